// round 1
// baseline (speedup 1.0000x reference)
#include <cuda_runtime.h>
#include <cstdint>

#define NPTS   400000
#define NXG    352
#define NYG    400
#define CANVAS 281600          // 2 * 1 * 400 * 352
#define BNEPS  1e-3f

// ---------------- scratch (static __device__ — no allocation allowed) ----------------
static __device__ int    g_idx[NPTS];
static __device__ float  g_vsum[CANVAS * 3];
static __device__ float  g_vcnt[CANVAS];
static __device__ float  g_z0[(size_t)NPTS * 64];      // z0, then pf0 in place
static __device__ float  g_v0[(size_t)CANVAS * 64];    // voxel max of pf0
static __device__ float  g_z1[(size_t)NPTS * 128];
static __device__ double g_stats[512];                 // s0[0:64] q0[64:128] s1[128:256] q1[256:384]
static __device__ float  g_ab[384];                    // a0[0:64] c0[64:128] a1[128:256] c1[256:384]

// ---------------- K1: voxel index + scatter-mean accumulators ----------------
__global__ void k_scatter(const float4* __restrict__ feats, const int4* __restrict__ coors)
{
    int p = blockIdx.x * 256 + threadIdx.x;
    if (p >= NPTS) return;
    int4 c = coors[p];                                    // [b, z, y, x], NZ == 1
    int idx = ((c.x + c.y) * NYG + c.z) * NXG + c.w;      // ((b*NZ+z)*NY+y)*NX+x
    g_idx[p] = idx;
    float4 f = feats[p];
    atomicAdd(&g_vsum[idx * 3 + 0], f.x);
    atomicAdd(&g_vsum[idx * 3 + 1], f.y);
    atomicAdd(&g_vsum[idx * 3 + 2], f.z);
    atomicAdd(&g_vcnt[idx], 1.0f);
}

// ---------------- K2: build 10-d feature, z0 = feat @ W0, coalesced store ----------------
__global__ void k_feat0(const float4* __restrict__ feats, const int4* __restrict__ coors,
                        const float* __restrict__ W0)
{
    __shared__ float Ws[640];
    __shared__ float outS[128 * 65];     // padded rows: conflict-free writes
    int t  = threadIdx.x;
    int p0 = blockIdx.x * 128;
    for (int i = t; i < 640; i += 128) Ws[i] = W0[i];

    int p = p0 + t;                       // 400000 % 128 == 0
    int4  c = coors[p];
    float4 f = feats[p];
    int   idx = g_idx[p];
    float inv = 1.0f / g_vcnt[idx];       // count >= 1 for occupied voxels
    float mx = g_vsum[idx * 3 + 0] * inv;
    float my = g_vsum[idx * 3 + 1] * inv;
    float mz = g_vsum[idx * 3 + 2] * inv;

    float f10[10];
    f10[0] = f.x;  f10[1] = f.y;  f10[2] = f.z;  f10[3] = f.w;
    f10[4] = f.x - mx;  f10[5] = f.y - my;  f10[6] = f.z - mz;
    f10[7] = f.x - ((float)c.w * 0.2f + 0.1f);     // VX/2 + x_min
    f10[8] = f.y - ((float)c.z * 0.2f - 39.9f);    // VY/2 + y_min
    f10[9] = f.z - ((float)c.y * 4.0f - 1.0f);     // VZ/2 + z_min
    __syncthreads();

    #pragma unroll
    for (int j = 0; j < 64; j++) {
        float acc = 0.f;
        #pragma unroll
        for (int k = 0; k < 10; k++) acc = fmaf(f10[k], Ws[k * 64 + j], acc);
        outS[t * 65 + j] = acc;           // bank = (t + j) % 32: conflict-free
    }
    __syncthreads();

    float4* gout = (float4*)(g_z0 + (size_t)p0 * 64);
    #pragma unroll
    for (int it = 0; it < 16; it++) {
        int gid = t + it * 128;           // float4 id in [0, 2048)
        int row = gid >> 4;
        int col = (gid & 15) << 2;
        const float* s = &outS[row * 65 + col];
        gout[gid] = make_float4(s[0], s[1], s[2], s[3]);   // fully coalesced
    }
}

// ---------------- K3/K7: per-channel sum & sumsq (BN batch stats) ----------------
__global__ void k_stats(const float* __restrict__ x, int shift, int s_off)
{
    int nch = 1 << shift;
    int tid = blockIdx.x * blockDim.x + threadIdx.x;
    int c = tid & (nch - 1);
    int r = tid >> shift;
    int rstride = (gridDim.x * blockDim.x) >> shift;
    float acc = 0.f, acc2 = 0.f;
    for (; r < NPTS; r += rstride) {
        float v = x[((size_t)r << shift) + c];
        acc += v;
        acc2 = fmaf(v, v, acc2);
    }
    atomicAdd(&g_stats[s_off + c], (double)acc);
    atomicAdd(&g_stats[s_off + nch + c], (double)acc2);
}

// ---------------- K4/K8: fold BN stats + affine into a*x + c ----------------
__global__ void k_bnfin(const float* __restrict__ gamma, const float* __restrict__ beta,
                        int nch, int s_off, int ab_off)
{
    int c = threadIdx.x;
    if (c >= nch) return;
    double mu  = g_stats[s_off + c] * (1.0 / NPTS);
    double var = g_stats[s_off + nch + c] * (1.0 / NPTS) - mu * mu;   // biased var
    float rstd = rsqrtf((float)var + BNEPS);
    float a = gamma[c] * rstd;
    g_ab[ab_off + c]       = a;
    g_ab[ab_off + nch + c] = beta[c] - (float)mu * a;
}

// ---------------- K5: pf0 = relu(a*z0+c) in place, scatter-max into v0 ----------------
__global__ void k_relumax0()
{
    int tid = blockIdx.x * 256 + threadIdx.x;       // NPTS*64 = 25.6M
    int c = tid & 63;
    int p = tid >> 6;
    float v = fmaf(g_z0[tid], g_ab[c], g_ab[64 + c]);
    v = fmaxf(v, 0.f);
    g_z0[tid] = v;
    if (v > 0.f)     // non-negative floats: uint order == float order
        atomicMax((unsigned int*)&g_v0[((size_t)g_idx[p] << 6) + c], __float_as_uint(v));
}

// ---------------- K6: z1 = [pf0 | v0[idx]] @ W1  (gather fused into A-tile load) ----------------
__global__ void __launch_bounds__(128, 2) k_gemm(const float* __restrict__ W1)
{
    extern __shared__ float sm[];
    float* As = sm;                    // transposed A: [k=128][m=64], row pad 65
    float* Bs = sm + 128 * 65;         // W1: [k=128][n=128]
    __shared__ int sIdx[64];

    int t  = threadIdx.x;
    int m0 = blockIdx.x * 64;

    float4* Bs4 = (float4*)Bs;
    const float4* W14 = (const float4*)W1;
    #pragma unroll
    for (int i = 0; i < 32; i++) Bs4[t + i * 128] = W14[t + i * 128];
    if (t < 64) sIdx[t] = g_idx[m0 + t];
    __syncthreads();

    // A tile: feat1[m][k] = k<64 ? pf0[m][k] : v0[idx[m]][k-64]; store transposed
    if (t < 64) {
        #pragma unroll 4
        for (int m = 0; m < 64; m++)
            As[t * 65 + m] = g_z0[(size_t)(m0 + m) * 64 + t];
    } else {
        int k = t - 64;
        #pragma unroll 4
        for (int m = 0; m < 64; m++)
            As[t * 65 + m] = g_v0[((size_t)sIdx[m] << 6) + k];
    }
    __syncthreads();

    int ty = t >> 4, tx = t & 15;      // 8 x 16 thread tile
    float acc[8][8];
    #pragma unroll
    for (int i = 0; i < 8; i++)
        #pragma unroll
        for (int j = 0; j < 8; j++) acc[i][j] = 0.f;

    #pragma unroll 2
    for (int k = 0; k < 128; k++) {
        float a[8];
        #pragma unroll
        for (int i = 0; i < 8; i++) a[i] = As[k * 65 + ty + i * 8];  // conflict-free
        float4 q0 = Bs4[k * 32 + tx * 2];
        float4 q1 = Bs4[k * 32 + tx * 2 + 1];
        float bb[8] = {q0.x, q0.y, q0.z, q0.w, q1.x, q1.y, q1.z, q1.w};
        #pragma unroll
        for (int i = 0; i < 8; i++)
            #pragma unroll
            for (int j = 0; j < 8; j++)
                acc[i][j] = fmaf(a[i], bb[j], acc[i][j]);
    }

    #pragma unroll
    for (int i = 0; i < 8; i++) {
        float* dst = g_z1 + (size_t)(m0 + ty + i * 8) * 128 + tx * 8;
        ((float4*)dst)[0] = make_float4(acc[i][0], acc[i][1], acc[i][2], acc[i][3]);
        ((float4*)dst)[1] = make_float4(acc[i][4], acc[i][5], acc[i][6], acc[i][7]);
    }
}

// ---------------- K9: pf1 = relu(a*z1+c), scatter-max into dense output canvas ----------------
__global__ void k_relumax1(float* __restrict__ out)
{
    int tid = blockIdx.x * 256 + threadIdx.x;      // NPTS*128 = 51.2M
    int c = tid & 127;
    int p = tid >> 7;
    float v = fmaf(g_z1[tid], g_ab[128 + c], g_ab[256 + c]);
    v = fmaxf(v, 0.f);
    if (v > 0.f)
        atomicMax((unsigned int*)&out[((size_t)g_idx[p] << 7) + c], __float_as_uint(v));
}

// ---------------- launch ----------------
extern "C" void kernel_launch(void* const* d_in, const int* in_sizes, int n_in,
                              void* d_out, int out_size)
{
    const float* feats = (const float*)d_in[0];
    const int*   coors = (const int*)d_in[1];
    const float* W0 = (const float*)d_in[2];
    const float* g0 = (const float*)d_in[3];
    const float* b0 = (const float*)d_in[4];
    const float* W1 = (const float*)d_in[5];
    const float* g1 = (const float*)d_in[6];
    const float* b1 = (const float*)d_in[7];
    (void)in_sizes; (void)n_in;

    void *p_vsum, *p_vcnt, *p_v0, *p_stats, *p_z0, *p_z1;
    cudaGetSymbolAddress(&p_vsum,  g_vsum);
    cudaGetSymbolAddress(&p_vcnt,  g_vcnt);
    cudaGetSymbolAddress(&p_v0,    g_v0);
    cudaGetSymbolAddress(&p_stats, g_stats);
    cudaGetSymbolAddress(&p_z0,    g_z0);
    cudaGetSymbolAddress(&p_z1,    g_z1);

    cudaMemsetAsync(p_vsum,  0, sizeof(float) * CANVAS * 3, 0);
    cudaMemsetAsync(p_vcnt,  0, sizeof(float) * CANVAS, 0);
    cudaMemsetAsync(p_v0,    0, sizeof(float) * (size_t)CANVAS * 64, 0);
    cudaMemsetAsync(p_stats, 0, sizeof(double) * 512, 0);
    cudaMemsetAsync(d_out,   0, sizeof(float) * (size_t)out_size, 0);

    k_scatter<<<(NPTS + 255) / 256, 256>>>((const float4*)feats, (const int4*)coors);
    k_feat0<<<NPTS / 128, 128>>>((const float4*)feats, (const int4*)coors, W0);
    k_stats<<<512, 128>>>((const float*)p_z0, 6, 0);
    k_bnfin<<<1, 128>>>(g0, b0, 64, 0, 0);
    k_relumax0<<<(NPTS * 64) / 256, 256>>>();

    const int GEMM_SMEM = (128 * 65 + 128 * 128) * (int)sizeof(float);   // 98816 B
    cudaFuncSetAttribute(k_gemm, cudaFuncAttributeMaxDynamicSharedMemorySize, GEMM_SMEM);
    k_gemm<<<NPTS / 64, 128, GEMM_SMEM>>>(W1);

    k_stats<<<1024, 128>>>((const float*)p_z1, 7, 128);
    k_bnfin<<<1, 128>>>(g1, b1, 128, 128, 128);
    k_relumax1<<<NPTS / 2, 256>>>((float*)d_out);
}

// round 3
// speedup vs baseline: 1.9838x; 1.9838x over previous
#include <cuda_runtime.h>
#include <cuda_bf16.h>
#include <cstdint>
#include <cstring>

#define NPTS   400000
#define NXG    352
#define NYG    400
#define CANVAS 281600          // 2 * 1 * 400 * 352
#define BNEPS  1e-3f
#define NTILES (NPTS / 128)    // 3125

// ---------------- scratch (static __device__ — no allocation allowed) ----------------
static __device__ int    g_idx[NPTS];
static __device__ float  g_vsum[CANVAS * 3];
static __device__ float  g_vcnt[CANVAS];
static __device__ float  g_z0[(size_t)NPTS * 64];      // raw z0 (pre-BN)
static __device__ float  g_v0[(size_t)CANVAS * 64];    // voxel max of pf0
static __device__ float  g_z1[(size_t)NPTS * 128];
static __device__ double g_stats[512];                 // s0[0:64] q0[64:128] s1[128:256] q1[256:384]
static __device__ float  g_ab[384];                    // a0[0:64] c0[64:128] a1[128:256] c1[256:384]

// ================= helpers =================
__device__ __forceinline__ uint32_t smem_u32(const void* p) {
    uint32_t a;
    asm("{ .reg .u64 t; cvta.to.shared.u64 t, %1; cvt.u32.u64 %0, t; }" : "=r"(a) : "l"(p));
    return a;
}
__device__ __forceinline__ void ldsm_x4(uint32_t* r, uint32_t addr) {
    asm volatile("ldmatrix.sync.aligned.m8n8.x4.shared.b16 {%0,%1,%2,%3}, [%4];"
        : "=r"(r[0]), "=r"(r[1]), "=r"(r[2]), "=r"(r[3]) : "r"(addr));
}
__device__ __forceinline__ void ldsm_x2(uint32_t* r, uint32_t addr) {
    asm volatile("ldmatrix.sync.aligned.m8n8.x2.shared.b16 {%0,%1}, [%2];"
        : "=r"(r[0]), "=r"(r[1]) : "r"(addr));
}
__device__ __forceinline__ void mma16816(float* d, const uint32_t* a, const uint32_t* b) {
    asm volatile("mma.sync.aligned.m16n8k16.row.col.f32.bf16.bf16.f32 "
        "{%0,%1,%2,%3}, {%4,%5,%6,%7}, {%8,%9}, {%0,%1,%2,%3};"
        : "+f"(d[0]), "+f"(d[1]), "+f"(d[2]), "+f"(d[3])
        : "r"(a[0]), "r"(a[1]), "r"(a[2]), "r"(a[3]), "r"(b[0]), "r"(b[1]));
}
// hi/lo bf16 split of two floats, packed as bf16x2 words
__device__ __forceinline__ void split2(float x, float y, uint32_t& hi, uint32_t& lo) {
    __nv_bfloat16 hx = __float2bfloat16(x), hy = __float2bfloat16(y);
    float rx = x - __bfloat162float(hx), ry = y - __bfloat162float(hy);
    __nv_bfloat16 lx = __float2bfloat16(rx), ly = __float2bfloat16(ry);
    __nv_bfloat162 H = __halves2bfloat162(hx, hy);
    __nv_bfloat162 L = __halves2bfloat162(lx, ly);
    memcpy(&hi, &H, 4); memcpy(&lo, &L, 4);
}

// ---------------- K1: voxel index + scatter-mean accumulators ----------------
__global__ void k_scatter(const float4* __restrict__ feats, const int4* __restrict__ coors)
{
    int p = blockIdx.x * 256 + threadIdx.x;
    if (p >= NPTS) return;
    int4 c = coors[p];
    int idx = ((c.x + c.y) * NYG + c.z) * NXG + c.w;
    g_idx[p] = idx;
    float4 f = feats[p];
    atomicAdd(&g_vsum[idx * 3 + 0], f.x);
    atomicAdd(&g_vsum[idx * 3 + 1], f.y);
    atomicAdd(&g_vsum[idx * 3 + 2], f.z);
    atomicAdd(&g_vcnt[idx], 1.0f);
}

// ---------------- K2: build 10-d feature, z0 = feat @ W0, coalesced store ----------------
__global__ void k_feat0(const float4* __restrict__ feats, const int4* __restrict__ coors,
                        const float* __restrict__ W0)
{
    __shared__ float Ws[640];
    __shared__ float outS[128 * 65];
    int t  = threadIdx.x;
    int p0 = blockIdx.x * 128;
    for (int i = t; i < 640; i += 128) Ws[i] = W0[i];

    int p = p0 + t;
    int4  c = coors[p];
    float4 f = feats[p];
    int   idx = g_idx[p];
    float inv = 1.0f / g_vcnt[idx];
    float mx = g_vsum[idx * 3 + 0] * inv;
    float my = g_vsum[idx * 3 + 1] * inv;
    float mz = g_vsum[idx * 3 + 2] * inv;

    float f10[10];
    f10[0] = f.x;  f10[1] = f.y;  f10[2] = f.z;  f10[3] = f.w;
    f10[4] = f.x - mx;  f10[5] = f.y - my;  f10[6] = f.z - mz;
    f10[7] = f.x - ((float)c.w * 0.2f + 0.1f);
    f10[8] = f.y - ((float)c.z * 0.2f - 39.9f);
    f10[9] = f.z - ((float)c.y * 4.0f - 1.0f);
    __syncthreads();

    #pragma unroll
    for (int j = 0; j < 64; j++) {
        float acc = 0.f;
        #pragma unroll
        for (int k = 0; k < 10; k++) acc = fmaf(f10[k], Ws[k * 64 + j], acc);
        outS[t * 65 + j] = acc;
    }
    __syncthreads();

    float4* gout = (float4*)(g_z0 + (size_t)p0 * 64);
    #pragma unroll
    for (int it = 0; it < 16; it++) {
        int gid = t + it * 128;
        int row = gid >> 4;
        int col = (gid & 15) << 2;
        const float* s = &outS[row * 65 + col];
        gout[gid] = make_float4(s[0], s[1], s[2], s[3]);
    }
}

// ---------------- K3: per-channel sum & sumsq of z0 (BN0 batch stats) ----------------
__global__ void k_stats(const float* __restrict__ x, int shift, int s_off)
{
    int nch = 1 << shift;
    int tid = blockIdx.x * blockDim.x + threadIdx.x;
    int c = tid & (nch - 1);
    int r = tid >> shift;
    int rstride = (gridDim.x * blockDim.x) >> shift;
    float acc = 0.f, acc2 = 0.f;
    for (; r < NPTS; r += rstride) {
        float v = x[((size_t)r << shift) + c];
        acc += v;
        acc2 = fmaf(v, v, acc2);
    }
    atomicAdd(&g_stats[s_off + c], (double)acc);
    atomicAdd(&g_stats[s_off + nch + c], (double)acc2);
}

// ---------------- K4/K8: fold BN stats + affine into a*x + c ----------------
__global__ void k_bnfin(const float* __restrict__ gamma, const float* __restrict__ beta,
                        int nch, int s_off, int ab_off)
{
    int c = threadIdx.x;
    if (c >= nch) return;
    double mu  = g_stats[s_off + c] * (1.0 / NPTS);
    double var = g_stats[s_off + nch + c] * (1.0 / NPTS) - mu * mu;
    float rstd = rsqrtf((float)var + BNEPS);
    float a = gamma[c] * rstd;
    g_ab[ab_off + c]       = a;
    g_ab[ab_off + nch + c] = beta[c] - (float)mu * a;
}

// ---------------- K5: relu(a*z0+c), scatter-max into v0 ----------------
__global__ void k_relumax0()
{
    int tid = blockIdx.x * 256 + threadIdx.x;
    int c = tid & 63;
    int p = tid >> 6;
    float v = fmaf(g_z0[tid], g_ab[c], g_ab[64 + c]);
    v = fmaxf(v, 0.f);
    if (v > 0.f)
        atomicMax((unsigned int*)&g_v0[((size_t)g_idx[p] << 6) + c], __float_as_uint(v));
}

// ---------------- K6: mma.sync bf16 GEMM  z1 = [relu(bn0(z0)) | v0[idx]] @ W1 ----------------
// Persistent, 148 CTAs x 256 thr. W1^T is the MMA "A" operand (m-role = channels):
// weight frags live in registers across all tiles. Hi/lo split, 3-term fp32 accum.
// Smem: AW planes (W1T hi, lo) then F planes (feat hi, lo); rows 272B (136 bf16) padded.
#define ROWB   272
#define PLANE  (128 * ROWB)     // 34816
#define F_BASE (2 * PLANE)      // 69632
#define GSMEM  (4 * PLANE)      // 139264

__global__ void __launch_bounds__(256, 1) k_gemm_mma(const float* __restrict__ W1)
{
    extern __shared__ char sm[];
    uint32_t sbase = smem_u32(sm);
    int t = threadIdx.x, w = t >> 5, lane = t & 31;
    int n0 = w * 16;

    // one-time: W1^T hi/lo planes in smem (row n, col k)
    for (int i = t; i < 16384; i += 256) {
        int k = i >> 7, n = i & 127;
        float v = W1[i];
        __nv_bfloat16 h = __float2bfloat16(v);
        __nv_bfloat16 l = __float2bfloat16(v - __bfloat162float(h));
        *(__nv_bfloat16*)(sm + n * ROWB + 2 * k) = h;
        *(__nv_bfloat16*)(sm + PLANE + n * ROWB + 2 * k) = l;
    }
    __syncthreads();

    // weight fragments: registers, persistent across tiles
    uint32_t Ah[8][4], Al[8][4];
    {
        int g = lane >> 3, r8 = lane & 7;
        uint32_t row = (uint32_t)(n0 + (g & 1) * 8 + r8) * ROWB + (uint32_t)((g >> 1) * 16);
        #pragma unroll
        for (int ks = 0; ks < 8; ks++) {
            ldsm_x4(Ah[ks], sbase + row + ks * 32);
            ldsm_x4(Al[ks], sbase + PLANE + row + ks * 32);
        }
    }

    // BN0 constants for channel pair 2*lane (used in feat build)
    float ba0 = g_ab[2 * lane],     bc0 = g_ab[64 + 2 * lane];
    float ba1 = g_ab[2 * lane + 1], bc1 = g_ab[64 + 2 * lane + 1];

    // layer-1 stats partials (channels c = n0+lane/4 and c+8)
    float s1 = 0.f, q1 = 0.f, s2 = 0.f, q2 = 0.f;

    int bl = lane & 15;
    uint32_t baddr0 = sbase + F_BASE + (uint32_t)((bl & 7) * ROWB + (bl >> 3) * 16);

    for (int tile = blockIdx.x; tile < NTILES; tile += gridDim.x) {
        int m0 = tile * 128;
        __syncthreads();                       // prev tile's ldmatrix reads done

        // feat tile build: warp w rows [w*16, w*16+16), lane covers channel pair 2*lane
        #pragma unroll 4
        for (int rr = 0; rr < 16; rr++) {
            int r = w * 16 + rr;
            int gm = m0 + r;
            int idxr = g_idx[gm];              // warp-broadcast load
            float2 z = *(const float2*)(g_z0 + (size_t)gm * 64 + 2 * lane);
            float p0 = fmaxf(fmaf(z.x, ba0, bc0), 0.f);
            float p1 = fmaxf(fmaf(z.y, ba1, bc1), 0.f);
            uint32_t hi, lo;
            split2(p0, p1, hi, lo);
            char* rp = sm + F_BASE + r * ROWB + 4 * lane;
            *(uint32_t*)(rp)         = hi;
            *(uint32_t*)(rp + PLANE) = lo;
            float2 gv = *(const float2*)(g_v0 + ((size_t)idxr << 6) + 2 * lane);
            split2(gv.x, gv.y, hi, lo);
            *(uint32_t*)(rp + 128)         = hi;
            *(uint32_t*)(rp + PLANE + 128) = lo;
        }
        __syncthreads();

        #pragma unroll 2
        for (int mb = 0; mb < 16; mb++) {
            float acc[4] = {0.f, 0.f, 0.f, 0.f};
            uint32_t ab = baddr0 + (uint32_t)(mb * 8 * ROWB);
            #pragma unroll
            for (int ks = 0; ks < 8; ks++) {
                uint32_t Bh[2], Bl[2];
                ldsm_x2(Bh, ab + ks * 32);
                ldsm_x2(Bl, ab + PLANE + ks * 32);
                mma16816(acc, Ah[ks], Bh);
                mma16816(acc, Al[ks], Bh);
                mma16816(acc, Ah[ks], Bl);
            }
            // epilogue: d0/d1 -> (m, m+1) x channel c; d2/d3 -> channel c+8
            int mloc = mb * 8 + (lane & 3) * 2;
            int c = n0 + (lane >> 2);
            float* dst = g_z1 + (size_t)(m0 + mloc) * 128 + c;
            dst[0]   = acc[0];
            dst[128] = acc[1];
            dst[8]   = acc[2];
            dst[136] = acc[3];
            s1 += acc[0] + acc[1];  q1 += acc[0] * acc[0] + acc[1] * acc[1];
            s2 += acc[2] + acc[3];  q2 += acc[2] * acc[2] + acc[3] * acc[3];
        }
    }

    // fused layer-1 BN stats: reduce over the 4 lanes sharing each channel
    #pragma unroll
    for (int off = 1; off <= 2; off <<= 1) {
        s1 += __shfl_xor_sync(0xffffffffu, s1, off);
        q1 += __shfl_xor_sync(0xffffffffu, q1, off);
        s2 += __shfl_xor_sync(0xffffffffu, s2, off);
        q2 += __shfl_xor_sync(0xffffffffu, q2, off);
    }
    if ((lane & 3) == 0) {
        int c = n0 + (lane >> 2);
        atomicAdd(&g_stats[128 + c],     (double)s1);
        atomicAdd(&g_stats[256 + c],     (double)q1);
        atomicAdd(&g_stats[128 + c + 8], (double)s2);
        atomicAdd(&g_stats[256 + c + 8], (double)q2);
    }
}

// ---------------- K9: pf1 = relu(a*z1+c), scatter-max into dense output canvas ----------------
__global__ void k_relumax1(float* __restrict__ out)
{
    int tid = blockIdx.x * 256 + threadIdx.x;
    int c = tid & 127;
    int p = tid >> 7;
    float v = fmaf(g_z1[tid], g_ab[128 + c], g_ab[256 + c]);
    v = fmaxf(v, 0.f);
    if (v > 0.f)
        atomicMax((unsigned int*)&out[((size_t)g_idx[p] << 7) + c], __float_as_uint(v));
}

// ---------------- launch ----------------
extern "C" void kernel_launch(void* const* d_in, const int* in_sizes, int n_in,
                              void* d_out, int out_size)
{
    const float* feats = (const float*)d_in[0];
    const int*   coors = (const int*)d_in[1];
    const float* W0 = (const float*)d_in[2];
    const float* g0 = (const float*)d_in[3];
    const float* b0 = (const float*)d_in[4];
    const float* W1 = (const float*)d_in[5];
    const float* g1 = (const float*)d_in[6];
    const float* b1 = (const float*)d_in[7];
    (void)in_sizes; (void)n_in;

    void *p_vsum, *p_vcnt, *p_v0, *p_stats, *p_z0;
    cudaGetSymbolAddress(&p_vsum,  g_vsum);
    cudaGetSymbolAddress(&p_vcnt,  g_vcnt);
    cudaGetSymbolAddress(&p_v0,    g_v0);
    cudaGetSymbolAddress(&p_stats, g_stats);
    cudaGetSymbolAddress(&p_z0,    g_z0);

    cudaMemsetAsync(p_vsum,  0, sizeof(float) * CANVAS * 3, 0);
    cudaMemsetAsync(p_vcnt,  0, sizeof(float) * CANVAS, 0);
    cudaMemsetAsync(p_v0,    0, sizeof(float) * (size_t)CANVAS * 64, 0);
    cudaMemsetAsync(p_stats, 0, sizeof(double) * 512, 0);
    cudaMemsetAsync(d_out,   0, sizeof(float) * (size_t)out_size, 0);

    k_scatter<<<(NPTS + 255) / 256, 256>>>((const float4*)feats, (const int4*)coors);
    k_feat0<<<NPTS / 128, 128>>>((const float4*)feats, (const int4*)coors, W0);
    k_stats<<<512, 128>>>((const float*)p_z0, 6, 0);
    k_bnfin<<<1, 128>>>(g0, b0, 64, 0, 0);
    k_relumax0<<<(NPTS * 64) / 256, 256>>>();

    cudaFuncSetAttribute(k_gemm_mma, cudaFuncAttributeMaxDynamicSharedMemorySize, GSMEM);
    k_gemm_mma<<<148, 256, GSMEM>>>(W1);    // also accumulates layer-1 BN stats

    k_bnfin<<<1, 128>>>(g1, b1, 128, 128, 128);
    k_relumax1<<<NPTS / 2, 256>>>((float*)d_out);
}

// round 4
// speedup vs baseline: 2.9806x; 1.5024x over previous
#include <cuda_runtime.h>
#include <cuda_bf16.h>
#include <cstdint>
#include <cstring>

#define NPTS   400000
#define NXG    352
#define NYG    400
#define CANVAS 281600          // 2 * 1 * 400 * 352
#define BNEPS  1e-3f
#define NTILES (NPTS / 128)    // 3125

// ---------------- scratch (static __device__ — no allocation allowed) ----------------
static __device__ int    g_idx[NPTS];
static __device__ float  g_vsum[CANVAS * 3];
static __device__ float  g_vcnt[CANVAS];
static __device__ float  g_z0[(size_t)NPTS * 64];      // raw z0 (pre-BN)
static __device__ float  g_v0[(size_t)CANVAS * 64];    // voxel max of pf0
static __device__ float  g_z1[(size_t)NPTS * 128];
static __device__ double g_stats[512];                 // s0[0:64] q0[64:128] s1[128:256] q1[256:384]
static __device__ float  g_ab[384];                    // a0[0:64] c0[64:128] a1[128:256] c1[256:384]

// ================= helpers =================
__device__ __forceinline__ uint32_t smem_u32(const void* p) {
    uint32_t a;
    asm("{ .reg .u64 t; cvta.to.shared.u64 t, %1; cvt.u32.u64 %0, t; }" : "=r"(a) : "l"(p));
    return a;
}
__device__ __forceinline__ void ldsm_x4(uint32_t* r, uint32_t addr) {
    asm volatile("ldmatrix.sync.aligned.m8n8.x4.shared.b16 {%0,%1,%2,%3}, [%4];"
        : "=r"(r[0]), "=r"(r[1]), "=r"(r[2]), "=r"(r[3]) : "r"(addr));
}
__device__ __forceinline__ void ldsm_x2(uint32_t* r, uint32_t addr) {
    asm volatile("ldmatrix.sync.aligned.m8n8.x2.shared.b16 {%0,%1}, [%2];"
        : "=r"(r[0]), "=r"(r[1]) : "r"(addr));
}
__device__ __forceinline__ void mma16816(float* d, const uint32_t* a, const uint32_t* b) {
    asm volatile("mma.sync.aligned.m16n8k16.row.col.f32.bf16.bf16.f32 "
        "{%0,%1,%2,%3}, {%4,%5,%6,%7}, {%8,%9}, {%0,%1,%2,%3};"
        : "+f"(d[0]), "+f"(d[1]), "+f"(d[2]), "+f"(d[3])
        : "r"(a[0]), "r"(a[1]), "r"(a[2]), "r"(a[3]), "r"(b[0]), "r"(b[1]));
}
__device__ __forceinline__ void cp16(uint32_t saddr, const void* g) {
    asm volatile("cp.async.cg.shared.global [%0], [%1], 16;" :: "r"(saddr), "l"(g));
}
#define CP_COMMIT() asm volatile("cp.async.commit_group;" ::: "memory")
#define CP_WAIT0()  asm volatile("cp.async.wait_group 0;" ::: "memory")

// hi/lo bf16 split of two floats, packed as bf16x2 words
__device__ __forceinline__ void split2(float x, float y, uint32_t& hi, uint32_t& lo) {
    __nv_bfloat16 hx = __float2bfloat16(x), hy = __float2bfloat16(y);
    float rx = x - __bfloat162float(hx), ry = y - __bfloat162float(hy);
    __nv_bfloat16 lx = __float2bfloat16(rx), ly = __float2bfloat16(ry);
    __nv_bfloat162 H = __halves2bfloat162(hx, hy);
    __nv_bfloat162 L = __halves2bfloat162(lx, ly);
    memcpy(&hi, &H, 4); memcpy(&lo, &L, 4);
}

// ---------------- K1: voxel index + scatter-mean accumulators ----------------
__global__ void k_scatter(const float4* __restrict__ feats, const int4* __restrict__ coors)
{
    int p = blockIdx.x * 256 + threadIdx.x;
    if (p >= NPTS) return;
    int4 c = coors[p];
    int idx = ((c.x + c.y) * NYG + c.z) * NXG + c.w;
    g_idx[p] = idx;
    float4 f = feats[p];
    atomicAdd(&g_vsum[idx * 3 + 0], f.x);
    atomicAdd(&g_vsum[idx * 3 + 1], f.y);
    atomicAdd(&g_vsum[idx * 3 + 2], f.z);
    atomicAdd(&g_vcnt[idx], 1.0f);
}

// ---------------- K2: 10-d feature, z0 = feat @ W0, fused BN0 batch stats ----------------
__global__ void k_feat0(const float4* __restrict__ feats, const int4* __restrict__ coors,
                        const float* __restrict__ W0)
{
    __shared__ float Ws[640];
    __shared__ float outS[128 * 65];
    int t  = threadIdx.x;
    int p0 = blockIdx.x * 128;
    for (int i = t; i < 640; i += 128) Ws[i] = W0[i];

    int p = p0 + t;
    int4  c = coors[p];
    float4 f = feats[p];
    int   idx = g_idx[p];
    float inv = 1.0f / g_vcnt[idx];
    float mx = g_vsum[idx * 3 + 0] * inv;
    float my = g_vsum[idx * 3 + 1] * inv;
    float mz = g_vsum[idx * 3 + 2] * inv;

    float f10[10];
    f10[0] = f.x;  f10[1] = f.y;  f10[2] = f.z;  f10[3] = f.w;
    f10[4] = f.x - mx;  f10[5] = f.y - my;  f10[6] = f.z - mz;
    f10[7] = f.x - ((float)c.w * 0.2f + 0.1f);
    f10[8] = f.y - ((float)c.z * 0.2f - 39.9f);
    f10[9] = f.z - ((float)c.y * 4.0f - 1.0f);
    __syncthreads();

    #pragma unroll
    for (int j = 0; j < 64; j++) {
        float acc = 0.f;
        #pragma unroll
        for (int k = 0; k < 10; k++) acc = fmaf(f10[k], Ws[k * 64 + j], acc);
        outS[t * 65 + j] = acc;
    }
    __syncthreads();

    // coalesced z0 store
    float4* gout = (float4*)(g_z0 + (size_t)p0 * 64);
    #pragma unroll
    for (int it = 0; it < 16; it++) {
        int gid = t + it * 128;
        int row = gid >> 4;
        int col = (gid & 15) << 2;
        const float* s = &outS[row * 65 + col];
        gout[gid] = make_float4(s[0], s[1], s[2], s[3]);
    }

    // fused BN0 stats: thread t sums 64 rows of channel (t & 63)
    {
        int ch = t & 63;
        int r0 = (t >> 6) * 64;
        float s = 0.f, q = 0.f;
        #pragma unroll 8
        for (int r = 0; r < 64; r++) {
            float v = outS[(r0 + r) * 65 + ch];
            s += v;
            q = fmaf(v, v, q);
        }
        atomicAdd(&g_stats[ch], (double)s);
        atomicAdd(&g_stats[64 + ch], (double)q);
    }
}

// ---------------- K4/K8: fold BN stats + affine into a*x + c ----------------
__global__ void k_bnfin(const float* __restrict__ gamma, const float* __restrict__ beta,
                        int nch, int s_off, int ab_off)
{
    int c = threadIdx.x;
    if (c >= nch) return;
    double mu  = g_stats[s_off + c] * (1.0 / NPTS);
    double var = g_stats[s_off + nch + c] * (1.0 / NPTS) - mu * mu;
    float rstd = rsqrtf((float)var + BNEPS);
    float a = gamma[c] * rstd;
    g_ab[ab_off + c]       = a;
    g_ab[ab_off + nch + c] = beta[c] - (float)mu * a;
}

// ---------------- K5: relu(a*z0+c), scatter-max into v0 (float4) ----------------
__global__ void k_relumax0()
{
    int tid = blockIdx.x * 256 + threadIdx.x;       // NPTS*16 threads
    int c4 = (tid & 15) << 2;
    int p  = tid >> 4;
    float4 z = *(const float4*)(g_z0 + ((size_t)p << 6) + c4);
    float4 a = *(const float4*)(g_ab + c4);
    float4 b = *(const float4*)(g_ab + 64 + c4);
    float v0 = fmaxf(fmaf(z.x, a.x, b.x), 0.f);
    float v1 = fmaxf(fmaf(z.y, a.y, b.y), 0.f);
    float v2 = fmaxf(fmaf(z.z, a.z, b.z), 0.f);
    float v3 = fmaxf(fmaf(z.w, a.w, b.w), 0.f);
    unsigned int* dst = (unsigned int*)(g_v0 + ((size_t)g_idx[p] << 6) + c4);
    if (v0 > 0.f) atomicMax(dst + 0, __float_as_uint(v0));
    if (v1 > 0.f) atomicMax(dst + 1, __float_as_uint(v1));
    if (v2 > 0.f) atomicMax(dst + 2, __float_as_uint(v2));
    if (v3 > 0.f) atomicMax(dst + 3, __float_as_uint(v3));
}

// ---------------- K6: pipelined mma.sync bf16 GEMM ----------------
// z1 = [relu(bn0(z0)) | v0[idx]] @ W1. Persistent 148 CTAs x 256 thr.
// W1^T frags register-resident. cp.async prefetch of next tile (z0 slab + v0 gather)
// into smem staging overlaps the current tile's mma loop.
#define ROWB    272
#define PLANE   (128 * ROWB)        // 34816
#define FBASE   (2 * PLANE)         // feat planes hi/lo after weight planes
#define STAGE_Z (4 * PLANE)         // 139264: raw z0 tile (32 KB)
#define STAGE_V (STAGE_Z + 32768)   // raw v0 gather (32 KB)
#define GSMEM   (STAGE_V + 32768)   // 204800

__device__ __forceinline__ void prefetch_tile(uint32_t sbase, int m0, int t)
{
    const char* zg = (const char*)(g_z0 + ((size_t)m0 << 6));
    #pragma unroll
    for (int i = 0; i < 8; i++) {
        int ch = t + i * 256;                      // 0..2047 16B chunks
        cp16(sbase + STAGE_Z + ch * 16, zg + ch * 16);
    }
    #pragma unroll
    for (int i = 0; i < 8; i++) {
        int ch = t + i * 256;
        int r = ch >> 4, j = ch & 15;
        const char* vg = (const char*)(g_v0 + ((size_t)g_idx[m0 + r] << 6)) + j * 16;
        cp16(sbase + STAGE_V + ch * 16, vg);
    }
    CP_COMMIT();
}

__global__ void __launch_bounds__(256, 1) k_gemm_mma(const float* __restrict__ W1)
{
    extern __shared__ char sm[];
    uint32_t sbase = smem_u32(sm);
    int t = threadIdx.x, w = t >> 5, lane = t & 31;
    int n0 = w * 16;

    // one-time: W1^T hi/lo planes (row n, col k)
    for (int i = t; i < 16384; i += 256) {
        int k = i >> 7, n = i & 127;
        float v = W1[i];
        __nv_bfloat16 h = __float2bfloat16(v);
        __nv_bfloat16 l = __float2bfloat16(v - __bfloat162float(h));
        *(__nv_bfloat16*)(sm + n * ROWB + 2 * k) = h;
        *(__nv_bfloat16*)(sm + PLANE + n * ROWB + 2 * k) = l;
    }
    __syncthreads();

    // weight fragments: registers, persistent across tiles
    uint32_t Ah[8][4], Al[8][4];
    {
        int g = lane >> 3, r8 = lane & 7;
        uint32_t row = (uint32_t)(n0 + (g & 1) * 8 + r8) * ROWB + (uint32_t)((g >> 1) * 16);
        #pragma unroll
        for (int ks = 0; ks < 8; ks++) {
            ldsm_x4(Ah[ks], sbase + row + ks * 32);
            ldsm_x4(Al[ks], sbase + PLANE + row + ks * 32);
        }
    }

    float ba0 = g_ab[2 * lane],     bc0 = g_ab[64 + 2 * lane];
    float ba1 = g_ab[2 * lane + 1], bc1 = g_ab[64 + 2 * lane + 1];

    float s1 = 0.f, q1 = 0.f, s2 = 0.f, q2 = 0.f;

    int bl = lane & 15;
    uint32_t baddr0 = sbase + FBASE + (uint32_t)((bl & 7) * ROWB + (bl >> 3) * 16);

    int tile = blockIdx.x;
    if (tile < NTILES) prefetch_tile(sbase, tile * 128, t);

    for (; tile < NTILES; tile += gridDim.x) {
        int m0 = tile * 128;
        CP_WAIT0();
        __syncthreads();                          // staged data visible; prev mma done

        // build feat planes from stage: warp w rows [w*16, w*16+16)
        #pragma unroll 4
        for (int rr = 0; rr < 16; rr++) {
            int r = w * 16 + rr;
            float2 z = *(const float2*)(sm + STAGE_Z + r * 256 + 8 * lane);
            float p0 = fmaxf(fmaf(z.x, ba0, bc0), 0.f);
            float p1 = fmaxf(fmaf(z.y, ba1, bc1), 0.f);
            uint32_t hi, lo;
            split2(p0, p1, hi, lo);
            char* rp = sm + FBASE + r * ROWB + 4 * lane;
            *(uint32_t*)(rp)         = hi;
            *(uint32_t*)(rp + PLANE) = lo;
            float2 gv = *(const float2*)(sm + STAGE_V + r * 256 + 8 * lane);
            split2(gv.x, gv.y, hi, lo);
            *(uint32_t*)(rp + 128)         = hi;
            *(uint32_t*)(rp + PLANE + 128) = lo;
        }
        __syncthreads();

        // prefetch next tile while mma runs
        int nxt = tile + gridDim.x;
        if (nxt < NTILES) prefetch_tile(sbase, nxt * 128, t);

        #pragma unroll 2
        for (int mb = 0; mb < 16; mb++) {
            float acc[4] = {0.f, 0.f, 0.f, 0.f};
            uint32_t ab = baddr0 + (uint32_t)(mb * 8 * ROWB);
            #pragma unroll
            for (int ks = 0; ks < 8; ks++) {
                uint32_t Bh[2], Bl[2];
                ldsm_x2(Bh, ab + ks * 32);
                ldsm_x2(Bl, ab + PLANE + ks * 32);
                mma16816(acc, Ah[ks], Bh);
                mma16816(acc, Al[ks], Bh);
                mma16816(acc, Ah[ks], Bl);
            }
            int mloc = mb * 8 + (lane & 3) * 2;
            int c = n0 + (lane >> 2);
            float* dst = g_z1 + (size_t)(m0 + mloc) * 128 + c;
            dst[0]   = acc[0];
            dst[128] = acc[1];
            dst[8]   = acc[2];
            dst[136] = acc[3];
            s1 += acc[0] + acc[1];  q1 += acc[0] * acc[0] + acc[1] * acc[1];
            s2 += acc[2] + acc[3];  q2 += acc[2] * acc[2] + acc[3] * acc[3];
        }
    }

    // fused layer-1 BN stats: reduce over the 4 lanes sharing each channel
    #pragma unroll
    for (int off = 1; off <= 2; off <<= 1) {
        s1 += __shfl_xor_sync(0xffffffffu, s1, off);
        q1 += __shfl_xor_sync(0xffffffffu, q1, off);
        s2 += __shfl_xor_sync(0xffffffffu, s2, off);
        q2 += __shfl_xor_sync(0xffffffffu, q2, off);
    }
    if ((lane & 3) == 0) {
        int c = n0 + (lane >> 2);
        atomicAdd(&g_stats[128 + c],     (double)s1);
        atomicAdd(&g_stats[256 + c],     (double)q1);
        atomicAdd(&g_stats[128 + c + 8], (double)s2);
        atomicAdd(&g_stats[256 + c + 8], (double)q2);
    }
}

// ---------------- K9: pf1 = relu(a*z1+c), scatter-max into dense output (float4) ----------------
__global__ void k_relumax1(float* __restrict__ out)
{
    int tid = blockIdx.x * 256 + threadIdx.x;     // NPTS*32 threads
    int c4 = (tid & 31) << 2;
    int p  = tid >> 5;
    float4 z = *(const float4*)(g_z1 + ((size_t)p << 7) + c4);
    float4 a = *(const float4*)(g_ab + 128 + c4);
    float4 b = *(const float4*)(g_ab + 256 + c4);
    float v0 = fmaxf(fmaf(z.x, a.x, b.x), 0.f);
    float v1 = fmaxf(fmaf(z.y, a.y, b.y), 0.f);
    float v2 = fmaxf(fmaf(z.z, a.z, b.z), 0.f);
    float v3 = fmaxf(fmaf(z.w, a.w, b.w), 0.f);
    unsigned int* dst = (unsigned int*)(out + ((size_t)g_idx[p] << 7) + c4);
    if (v0 > 0.f) atomicMax(dst + 0, __float_as_uint(v0));
    if (v1 > 0.f) atomicMax(dst + 1, __float_as_uint(v1));
    if (v2 > 0.f) atomicMax(dst + 2, __float_as_uint(v2));
    if (v3 > 0.f) atomicMax(dst + 3, __float_as_uint(v3));
}

// ---------------- launch ----------------
extern "C" void kernel_launch(void* const* d_in, const int* in_sizes, int n_in,
                              void* d_out, int out_size)
{
    const float* feats = (const float*)d_in[0];
    const int*   coors = (const int*)d_in[1];
    const float* W0 = (const float*)d_in[2];
    const float* g0 = (const float*)d_in[3];
    const float* b0 = (const float*)d_in[4];
    const float* W1 = (const float*)d_in[5];
    const float* g1 = (const float*)d_in[6];
    const float* b1 = (const float*)d_in[7];
    (void)in_sizes; (void)n_in;

    void *p_vsum, *p_vcnt, *p_v0, *p_stats;
    cudaGetSymbolAddress(&p_vsum,  g_vsum);
    cudaGetSymbolAddress(&p_vcnt,  g_vcnt);
    cudaGetSymbolAddress(&p_v0,    g_v0);
    cudaGetSymbolAddress(&p_stats, g_stats);

    cudaMemsetAsync(p_vsum,  0, sizeof(float) * CANVAS * 3, 0);
    cudaMemsetAsync(p_vcnt,  0, sizeof(float) * CANVAS, 0);
    cudaMemsetAsync(p_v0,    0, sizeof(float) * (size_t)CANVAS * 64, 0);
    cudaMemsetAsync(p_stats, 0, sizeof(double) * 512, 0);
    cudaMemsetAsync(d_out,   0, sizeof(float) * (size_t)out_size, 0);

    k_scatter<<<(NPTS + 255) / 256, 256>>>((const float4*)feats, (const int4*)coors);
    k_feat0<<<NPTS / 128, 128>>>((const float4*)feats, (const int4*)coors, W0);
    k_bnfin<<<1, 128>>>(g0, b0, 64, 0, 0);
    k_relumax0<<<(NPTS * 16) / 256, 256>>>();

    cudaFuncSetAttribute(k_gemm_mma, cudaFuncAttributeMaxDynamicSharedMemorySize, GSMEM);
    k_gemm_mma<<<148, 256, GSMEM>>>(W1);    // also accumulates layer-1 BN stats

    k_bnfin<<<1, 128>>>(g1, b1, 128, 128, 128);
    k_relumax1<<<(NPTS * 32) / 256, 256>>>((float*)d_out);
}